// round 14
// baseline (speedup 1.0000x reference)
#include <cuda_runtime.h>
#include <cuda_bf16.h>
#include <math.h>
#include <stdint.h>

#define N_NODES 50000
#define N_EDGESC 400000
#define H 128
#define NT 2
#define FEAT 4
#define TILE_E 128

// ---------------- device scratch (no runtime allocation) ----------------
__device__ float g_h[N_NODES * H];
__device__ float g_agg[N_NODES * H];
__device__ float g_gi[N_NODES * 3 * H];
__device__ int   g_perm[N_EDGESC];
__device__ int   g_cnt[2];
__device__ int   g_cursor[2];
// edge-MLP weights, transposed + bf16 hi/lo packed: word [lt][n][kw] = bf16(k=2kw), bf16(k=2kw+1)
__device__ uint32_t g_W1B_hi[6 * 128 * 128];
__device__ uint32_t g_W1B_lo[6 * 128 * 128];
__device__ uint32_t g_W2B_hi[6 * 128 * 64];
__device__ uint32_t g_W2B_lo[6 * 128 * 64];
// GRU ih weights (normal col order): [l][n(384)][kw(64)]
__device__ uint32_t g_WIB_hi[3 * 384 * 64];
__device__ uint32_t g_WIB_lo[3 * 384 * 64];
// GRU hh weights (permuted col order pn): [l][pn(384)][kw(64)]
__device__ uint32_t g_WHF_hi[3 * 384 * 64];
__device__ uint32_t g_WHF_lo[3 * 384 * 64];

__device__ __forceinline__ float sigm(float v) { return 1.0f / (1.0f + expf(-v)); }

__device__ __forceinline__ void split_pack(float x, float y, uint32_t& hi, uint32_t& lo) {
    __nv_bfloat162 h = __floats2bfloat162_rn(x, y);
    hi = reinterpret_cast<uint32_t&>(h);
    float rx = x - __low2float(h);
    float ry = y - __high2float(h);
    __nv_bfloat162 l = __floats2bfloat162_rn(rx, ry);
    lo = reinterpret_cast<uint32_t&>(l);
}

__device__ __forceinline__ void mma_bf16(float* c, uint32_t a0, uint32_t a1, uint32_t a2,
                                         uint32_t a3, uint32_t b0, uint32_t b1) {
    asm volatile(
        "mma.sync.aligned.m16n8k16.row.col.f32.bf16.bf16.f32 "
        "{%0,%1,%2,%3}, {%4,%5,%6,%7}, {%8,%9}, {%0,%1,%2,%3};"
        : "+f"(c[0]), "+f"(c[1]), "+f"(c[2]), "+f"(c[3])
        : "r"(a0), "r"(a1), "r"(a2), "r"(a3), "r"(b0), "r"(b1));
}

__device__ __forceinline__ void red2(float* p, float a, float b) {
    asm volatile("red.global.add.v2.f32 [%0], {%1, %2};" :: "l"(p), "f"(a), "f"(b) : "memory");
}

__device__ __forceinline__ void cp16(uint32_t saddr, const void* g) {
    asm volatile("cp.async.cg.shared.global [%0], [%1], 16;" :: "r"(saddr), "l"(g));
}
#define CP_COMMIT() asm volatile("cp.async.commit_group;" ::: "memory")
#define CP_WAIT0()  asm volatile("cp.async.wait_group 0;" ::: "memory")
#define CP_WAIT1()  asm volatile("cp.async.wait_group 1;" ::: "memory")

__device__ __forceinline__ uint32_t smem_u32(const void* p) {
    uint32_t a;
    asm("{ .reg .u64 t; cvta.to.shared.u64 t, %1; cvt.u32.u64 %0, t; }" : "=r"(a) : "l"(p));
    return a;
}

// ---------------- edge partition by type ----------------
__global__ void k_zero_cnt() { if (threadIdx.x < 2) g_cnt[threadIdx.x] = 0; }

__global__ void k_count(const int* __restrict__ et) {
    __shared__ int lc[2];
    if (threadIdx.x < 2) lc[threadIdx.x] = 0;
    __syncthreads();
    int e = blockIdx.x * blockDim.x + threadIdx.x;
    if (e < N_EDGESC) atomicAdd(&lc[et[e]], 1);
    __syncthreads();
    if (threadIdx.x < 2) atomicAdd(&g_cnt[threadIdx.x], lc[threadIdx.x]);
}

__global__ void k_seed() { g_cursor[0] = 0; g_cursor[1] = g_cnt[0]; }

__global__ void k_scatter(const int* __restrict__ et) {
    __shared__ int lc[2];
    __shared__ int base[2];
    if (threadIdx.x < 2) lc[threadIdx.x] = 0;
    __syncthreads();
    int e = blockIdx.x * blockDim.x + threadIdx.x;
    int t = 0, rank = 0;
    bool valid = (e < N_EDGESC);
    if (valid) { t = et[e]; rank = atomicAdd(&lc[t], 1); }
    __syncthreads();
    if (threadIdx.x < 2) base[threadIdx.x] = atomicAdd(&g_cursor[threadIdx.x], lc[threadIdx.x]);
    __syncthreads();
    if (valid) g_perm[base[t] + rank] = e;
}

// ---------------- weight transpose + bf16 split-pack (once per launch) ----------------
__global__ void k_prep_w(const float* __restrict__ W1, const float* __restrict__ W2) {
    int idx = blockIdx.x * blockDim.x + threadIdx.x;
    const int NW1 = 6 * 128 * 128;
    const int NW2 = 6 * 128 * 64;
    if (idx < NW1) {
        int lt = idx >> 14, rem = idx & 16383;
        int n = rem >> 7, kw = rem & 127;
        const float* base = W1 + (size_t)lt * 32768;
        float v0 = base[(2 * kw) * 128 + n];
        float v1 = base[(2 * kw + 1) * 128 + n];
        uint32_t hi, lo;
        split_pack(v0, v1, hi, lo);
        int o = lt * 16384 + n * 128 + kw;
        g_W1B_hi[o] = hi; g_W1B_lo[o] = lo;
    } else if (idx < NW1 + NW2) {
        int i2 = idx - NW1;
        int lt = i2 >> 13, rem = i2 & 8191;
        int n = rem >> 6, kw = rem & 63;
        const float* base = W2 + (size_t)lt * 16384;
        float v0 = base[(2 * kw) * 128 + n];
        float v1 = base[(2 * kw + 1) * 128 + n];
        uint32_t hi, lo;
        split_pack(v0, v1, hi, lo);
        int o = lt * 8192 + n * 64 + kw;
        g_W2B_hi[o] = hi; g_W2B_lo[o] = lo;
    }
}

__global__ void k_prep_gru(const float* __restrict__ Wih, const float* __restrict__ Whh) {
    int idx = blockIdx.x * blockDim.x + threadIdx.x;
    const int TOT = 2 * 3 * 384 * 64;
    if (idx >= TOT) return;
    int sel = idx / 73728, rem = idx % 73728;
    int l = rem / 24576, rem2 = rem % 24576;
    int n = rem2 >> 6, kw = rem2 & 63;
    const float* src = (sel ? Whh : Wih) + (size_t)l * H * 3 * H;
    float v0 = src[(2 * kw) * 384 + n];
    float v1 = src[(2 * kw + 1) * 384 + n];
    uint32_t hi, lo;
    split_pack(v0, v1, hi, lo);
    if (sel == 0) {
        int o = l * 24576 + n * 64 + kw;
        g_WIB_hi[o] = hi; g_WIB_lo[o] = lo;
    } else {
        // permute: col n -> pn so each warp holds matching (r,z,n) triples
        int part = n >> 7, cg = (n & 127) >> 5, cl = n & 31;
        int pn = cg * 96 + part * 32 + cl;
        int o = l * 24576 + pn * 64 + kw;
        g_WHF_hi[o] = hi; g_WHF_lo[o] = lo;
    }
}

// ---------------- h = relu(x @ W_in + b_in); also zero agg for layer 0 ----------------
__global__ void k_init(const float* __restrict__ x, const float* __restrict__ Win,
                       const float* __restrict__ bin) {
    __shared__ float sW[FEAT * H];
    __shared__ float sb[H];
    for (int i = threadIdx.x; i < FEAT * H; i += blockDim.x) sW[i] = Win[i];
    if (threadIdx.x < H) sb[threadIdx.x] = bin[threadIdx.x];
    __syncthreads();
    int idx = blockIdx.x * blockDim.x + threadIdx.x;
    if (idx >= N_NODES * H) return;
    int n = idx >> 7, c = idx & 127;
    float4 xr = ((const float4*)x)[n];
    float v = sb[c] + xr.x * sW[c] + xr.y * sW[H + c] + xr.z * sW[2 * H + c] + xr.w * sW[3 * H + c];
    g_h[idx] = fmaxf(v, 0.0f);
    g_agg[idx] = 0.0f;
}

// ---------------- edge MLP: bf16 hi/lo x3, pipelined (unchanged from R13) ----------------
#define A_STR 68
#define B_STR 20
#define F_AH 0
#define F_AL (128 * A_STR)
#define F_B  (2 * 128 * A_STR)
#define B_BUF_W (2 * 128 * B_STR)
#define F_META (F_B + 2 * B_BUF_W)
#define EDGE_SMEM ((F_META + 512) * 4)

__global__ __launch_bounds__(256, 2)
void k_edge_tc(const int* __restrict__ edge_index,
               const float* __restrict__ b1, const float* __restrict__ b2, int l) {
    extern __shared__ uint32_t smw[];
    uint32_t* sAh = smw + F_AH;
    uint32_t* sAl = smw + F_AL;
    int*   sSrc = (int*)(smw + F_META);
    int*   sDst = sSrc + 128;
    float* sB1  = (float*)(sDst + 128);
    float* sB2  = sB1 + 128;
    const uint32_t su = smem_u32(smw);

    int tid = threadIdx.x;
    int w = tid >> 5, lane = tid & 31;
    int gid = lane >> 2, tig = lane & 3;

    int cnt0 = g_cnt[0];
    int nb0 = (cnt0 + TILE_E - 1) / TILE_E;
    int type, start, cnt, permBase;
    if ((int)blockIdx.x < nb0) {
        type = 0; start = blockIdx.x * TILE_E; cnt = cnt0; permBase = 0;
    } else {
        type = 1; start = ((int)blockIdx.x - nb0) * TILE_E;
        cnt = N_EDGESC - cnt0; permBase = cnt0;
        if (start >= cnt) return;
    }
    int lt = l * NT + type;

    const uint32_t* w1h = g_W1B_hi + (size_t)lt * 16384;
    const uint32_t* w1l = g_W1B_lo + (size_t)lt * 16384;
    const uint32_t* w2h = g_W2B_hi + (size_t)lt * 8192;
    const uint32_t* w2l = g_W2B_lo + (size_t)lt * 8192;

    int nB = tid >> 1, offB = (tid & 1) * 8;

    {
        uint32_t dst = su + (F_B + nB * B_STR + offB) * 4;
        const uint32_t* gh_ = w1h + nB * 128 + offB;
        const uint32_t* gl_ = w1l + nB * 128 + offB;
        cp16(dst, gh_); cp16(dst + 16, gh_ + 4);
        cp16(dst + 128 * B_STR * 4, gl_); cp16(dst + 128 * B_STR * 4 + 16, gl_ + 4);
        CP_COMMIT();
    }

    if (tid < 128) {
        int g = start + tid; int s = -1, d = -1;
        if (g < cnt) { int e = g_perm[permBase + g]; s = edge_index[e]; d = edge_index[N_EDGESC + e]; }
        sSrc[tid] = s;
        sDst[tid] = d;
    } else {
        int c = tid - 128;
        sB1[c] = b1[lt * H + c];
        sB2[c] = b2[lt * H + c];
    }
    __syncthreads();

    float acc[16][4];
#pragma unroll
    for (int j = 0; j < 16; ++j)
#pragma unroll
        for (int q = 0; q < 4; ++q) acc[j][q] = 0.f;

    int rA0 = w * 16 + gid;
    int rA1 = rA0 + 8;

    float4 aCur[4], aNxt[4];
#pragma unroll
    for (int i = 0; i < 4; ++i) {
        int i0 = tid + i * 256, r = i0 >> 3, q = i0 & 7;
        int node = sSrc[r];
        aCur[i] = (node >= 0) ? *(const float4*)(g_h + (size_t)node * H + q * 4)
                              : make_float4(0.f, 0.f, 0.f, 0.f);
    }

    for (int kc = 0; kc < 8; ++kc) {
        int buf = kc & 1;
#pragma unroll
        for (int i = 0; i < 4; ++i) {
            int i0 = tid + i * 256, r = i0 >> 3, q = i0 & 7;
            uint32_t h0, l0, h1, l1;
            split_pack(aCur[i].x, aCur[i].y, h0, l0);
            split_pack(aCur[i].z, aCur[i].w, h1, l1);
            *(uint2*)(sAh + r * A_STR + q * 2) = make_uint2(h0, h1);
            *(uint2*)(sAl + r * A_STR + q * 2) = make_uint2(l0, l1);
        }
        if (kc < 7) {
            int kn = kc + 1;
#pragma unroll
            for (int i = 0; i < 4; ++i) {
                int i0 = tid + i * 256, r = i0 >> 3, q = i0 & 7;
                int node = (kn < 4) ? sSrc[r] : sDst[r];
                aNxt[i] = (node >= 0)
                    ? *(const float4*)(g_h + (size_t)node * H + (kn & 3) * 32 + q * 4)
                    : make_float4(0.f, 0.f, 0.f, 0.f);
            }
            uint32_t dst = su + (F_B + (buf ^ 1) * B_BUF_W + nB * B_STR + offB) * 4;
            const uint32_t* gh_ = w1h + nB * 128 + kn * 16 + offB;
            const uint32_t* gl_ = w1l + nB * 128 + kn * 16 + offB;
            cp16(dst, gh_); cp16(dst + 16, gh_ + 4);
            cp16(dst + 128 * B_STR * 4, gl_); cp16(dst + 128 * B_STR * 4 + 16, gl_ + 4);
            CP_COMMIT();
            CP_WAIT1();
        } else {
            CP_WAIT0();
        }
        __syncthreads();
        const uint32_t* sBh = smw + F_B + buf * B_BUF_W;
        const uint32_t* sBl = sBh + 128 * B_STR;
#pragma unroll
        for (int s = 0; s < 2; ++s) {
            int kwb = 8 * s;
            uint32_t ah0 = sAh[rA0 * A_STR + kwb + tig];
            uint32_t ah1 = sAh[rA1 * A_STR + kwb + tig];
            uint32_t ah2 = sAh[rA0 * A_STR + kwb + tig + 4];
            uint32_t ah3 = sAh[rA1 * A_STR + kwb + tig + 4];
            uint32_t al0 = sAl[rA0 * A_STR + kwb + tig];
            uint32_t al1 = sAl[rA1 * A_STR + kwb + tig];
            uint32_t al2 = sAl[rA0 * A_STR + kwb + tig + 4];
            uint32_t al3 = sAl[rA1 * A_STR + kwb + tig + 4];
#pragma unroll
            for (int j = 0; j < 16; ++j) {
                int nb = (j * 8 + gid) * B_STR + kwb + tig;
                uint32_t bh0 = sBh[nb], bh1 = sBh[nb + 4];
                uint32_t bl0 = sBl[nb], bl1 = sBl[nb + 4];
                mma_bf16(acc[j], ah0, ah1, ah2, ah3, bh0, bh1);
                mma_bf16(acc[j], al0, al1, al2, al3, bh0, bh1);
                mma_bf16(acc[j], ah0, ah1, ah2, ah3, bl0, bl1);
            }
        }
        __syncthreads();
#pragma unroll
        for (int i = 0; i < 4; ++i) aCur[i] = aNxt[i];
    }

    {
        uint32_t dst = su + (F_B + nB * B_STR + offB) * 4;
        const uint32_t* gh_ = w2h + nB * 64 + offB;
        const uint32_t* gl_ = w2l + nB * 64 + offB;
        cp16(dst, gh_); cp16(dst + 16, gh_ + 4);
        cp16(dst + 128 * B_STR * 4, gl_); cp16(dst + 128 * B_STR * 4 + 16, gl_ + 4);
        CP_COMMIT();
    }

#pragma unroll
    for (int j = 0; j < 16; ++j) {
        int col = j * 8 + 2 * tig;
        float ba = sB1[col], bb = sB1[col + 1];
        float v0x = fmaxf(acc[j][0] + ba, 0.f), v0y = fmaxf(acc[j][1] + bb, 0.f);
        float v1x = fmaxf(acc[j][2] + ba, 0.f), v1y = fmaxf(acc[j][3] + bb, 0.f);
        int kw = j * 4 + tig;
        uint32_t h, lo;
        split_pack(v0x, v0y, h, lo);
        sAh[rA0 * A_STR + kw] = h; sAl[rA0 * A_STR + kw] = lo;
        split_pack(v1x, v1y, h, lo);
        sAh[rA1 * A_STR + kw] = h; sAl[rA1 * A_STR + kw] = lo;
        acc[j][0] = acc[j][1] = acc[j][2] = acc[j][3] = 0.f;
    }

    for (int kc = 0; kc < 4; ++kc) {
        int buf = kc & 1;
        if (kc < 3) {
            int kn = kc + 1;
            uint32_t dst = su + (F_B + (buf ^ 1) * B_BUF_W + nB * B_STR + offB) * 4;
            const uint32_t* gh_ = w2h + nB * 64 + kn * 16 + offB;
            const uint32_t* gl_ = w2l + nB * 64 + kn * 16 + offB;
            cp16(dst, gh_); cp16(dst + 16, gh_ + 4);
            cp16(dst + 128 * B_STR * 4, gl_); cp16(dst + 128 * B_STR * 4 + 16, gl_ + 4);
            CP_COMMIT();
            CP_WAIT1();
        } else {
            CP_WAIT0();
        }
        __syncthreads();
        const uint32_t* sBh = smw + F_B + buf * B_BUF_W;
        const uint32_t* sBl = sBh + 128 * B_STR;
#pragma unroll
        for (int s = 0; s < 2; ++s) {
            int kwb = kc * 16 + 8 * s;
            uint32_t ah0 = sAh[rA0 * A_STR + kwb + tig];
            uint32_t ah1 = sAh[rA1 * A_STR + kwb + tig];
            uint32_t ah2 = sAh[rA0 * A_STR + kwb + tig + 4];
            uint32_t ah3 = sAh[rA1 * A_STR + kwb + tig + 4];
            uint32_t al0 = sAl[rA0 * A_STR + kwb + tig];
            uint32_t al1 = sAl[rA1 * A_STR + kwb + tig];
            uint32_t al2 = sAl[rA0 * A_STR + kwb + tig + 4];
            uint32_t al3 = sAl[rA1 * A_STR + kwb + tig + 4];
#pragma unroll
            for (int j = 0; j < 16; ++j) {
                int nb = (j * 8 + gid) * B_STR + 8 * s + tig;
                uint32_t bh0 = sBh[nb], bh1 = sBh[nb + 4];
                uint32_t bl0 = sBl[nb], bl1 = sBl[nb + 4];
                mma_bf16(acc[j], ah0, ah1, ah2, ah3, bh0, bh1);
                mma_bf16(acc[j], al0, al1, al2, al3, bh0, bh1);
                mma_bf16(acc[j], ah0, ah1, ah2, ah3, bl0, bl1);
            }
        }
        __syncthreads();
    }

    int d0 = sDst[rA0];
    int d1 = sDst[rA1];
#pragma unroll
    for (int j = 0; j < 16; ++j) {
        int col = j * 8 + 2 * tig;
        float ba = sB2[col], bb = sB2[col + 1];
        if (d0 >= 0) red2(g_agg + (size_t)d0 * H + col, acc[j][0] + ba, acc[j][1] + bb);
        if (d1 >= 0) red2(g_agg + (size_t)d1 * H + col, acc[j][2] + ba, acc[j][3] + bb);
    }
}

// ---------------- GRU gi GEMM: gi = agg @ W_ih + b_ih (pipelined, R13 structure) ----------------
#define A2_STR 20
#define G_AH 0
#define G_AL (128 * A2_STR)
#define G_B  (2 * 128 * A2_STR)
#define GB_BUF_W (2 * 128 * B_STR)
#define G_BIAS (G_B + 2 * GB_BUF_W)
#define GRU_SMEM ((G_BIAS + 128) * 4)

__global__ __launch_bounds__(256, 2)
void k_gru_gi(const float* __restrict__ bih, int l) {
    extern __shared__ uint32_t smw[];
    uint32_t* sAh = smw + G_AH;
    uint32_t* sAl = smw + G_AL;
    float* sBias = (float*)(smw + G_BIAS);
    const uint32_t su = smem_u32(smw);

    int tid = threadIdx.x;
    int w = tid >> 5, lane = tid & 31;
    int gid = lane >> 2, tig = lane & 3;

    const float* A = g_agg;
    float* C = g_gi;
    const float* b = bih + l * 3 * H;
    const uint32_t* wbh = g_WIB_hi + (size_t)l * 24576;
    const uint32_t* wbl = g_WIB_lo + (size_t)l * 24576;

    int m0 = blockIdx.x * 128;
    int c0 = blockIdx.y * 128;

    int nB = tid >> 1, offB = (tid & 1) * 8;

    {
        uint32_t dst = su + (G_B + nB * B_STR + offB) * 4;
        const uint32_t* gh_ = wbh + (size_t)(c0 + nB) * 64 + offB;
        const uint32_t* gl_ = wbl + (size_t)(c0 + nB) * 64 + offB;
        cp16(dst, gh_); cp16(dst + 16, gh_ + 4);
        cp16(dst + 128 * B_STR * 4, gl_); cp16(dst + 128 * B_STR * 4 + 16, gl_ + 4);
        CP_COMMIT();
    }

    if (tid < 128) sBias[tid] = b[c0 + tid];

    float acc[16][4];
#pragma unroll
    for (int j = 0; j < 16; ++j)
#pragma unroll
        for (int q = 0; q < 4; ++q) acc[j][q] = 0.f;

    int rA0 = w * 16 + gid;
    int rA1 = rA0 + 8;

    float4 aCur[4], aNxt[4];
#pragma unroll
    for (int i = 0; i < 4; ++i) {
        int i0 = tid + i * 256, r = i0 >> 3, q = i0 & 7;
        int m = m0 + r;
        aCur[i] = (m < N_NODES) ? *(const float4*)(A + (size_t)m * H + q * 4)
                                : make_float4(0.f, 0.f, 0.f, 0.f);
    }

    for (int kc = 0; kc < 4; ++kc) {
        int buf = kc & 1;
#pragma unroll
        for (int i = 0; i < 4; ++i) {
            int i0 = tid + i * 256, r = i0 >> 3, q = i0 & 7;
            uint32_t h0, l0, h1, l1;
            split_pack(aCur[i].x, aCur[i].y, h0, l0);
            split_pack(aCur[i].z, aCur[i].w, h1, l1);
            *(uint2*)(sAh + r * A2_STR + q * 2) = make_uint2(h0, h1);
            *(uint2*)(sAl + r * A2_STR + q * 2) = make_uint2(l0, l1);
        }
        if (kc < 3) {
            int kn = kc + 1;
#pragma unroll
            for (int i = 0; i < 4; ++i) {
                int i0 = tid + i * 256, r = i0 >> 3, q = i0 & 7;
                int m = m0 + r;
                aNxt[i] = (m < N_NODES)
                    ? *(const float4*)(A + (size_t)m * H + kn * 32 + q * 4)
                    : make_float4(0.f, 0.f, 0.f, 0.f);
            }
            uint32_t dst = su + (G_B + (buf ^ 1) * GB_BUF_W + nB * B_STR + offB) * 4;
            const uint32_t* gh_ = wbh + (size_t)(c0 + nB) * 64 + kn * 16 + offB;
            const uint32_t* gl_ = wbl + (size_t)(c0 + nB) * 64 + kn * 16 + offB;
            cp16(dst, gh_); cp16(dst + 16, gh_ + 4);
            cp16(dst + 128 * B_STR * 4, gl_); cp16(dst + 128 * B_STR * 4 + 16, gl_ + 4);
            CP_COMMIT();
            CP_WAIT1();
        } else {
            CP_WAIT0();
        }
        __syncthreads();
        const uint32_t* sBh = smw + G_B + buf * GB_BUF_W;
        const uint32_t* sBl = sBh + 128 * B_STR;
#pragma unroll
        for (int s = 0; s < 2; ++s) {
            int kwb = 8 * s;
            uint32_t ah0 = sAh[rA0 * A2_STR + kwb + tig];
            uint32_t ah1 = sAh[rA1 * A2_STR + kwb + tig];
            uint32_t ah2 = sAh[rA0 * A2_STR + kwb + tig + 4];
            uint32_t ah3 = sAh[rA1 * A2_STR + kwb + tig + 4];
            uint32_t al0 = sAl[rA0 * A2_STR + kwb + tig];
            uint32_t al1 = sAl[rA1 * A2_STR + kwb + tig];
            uint32_t al2 = sAl[rA0 * A2_STR + kwb + tig + 4];
            uint32_t al3 = sAl[rA1 * A2_STR + kwb + tig + 4];
#pragma unroll
            for (int j = 0; j < 16; ++j) {
                int nb = (j * 8 + gid) * B_STR + kwb + tig;
                uint32_t bh0 = sBh[nb], bh1 = sBh[nb + 4];
                uint32_t bl0 = sBl[nb], bl1 = sBl[nb + 4];
                mma_bf16(acc[j], ah0, ah1, ah2, ah3, bh0, bh1);
                mma_bf16(acc[j], al0, al1, al2, al3, bh0, bh1);
                mma_bf16(acc[j], ah0, ah1, ah2, ah3, bl0, bl1);
            }
        }
        __syncthreads();
#pragma unroll
        for (int i = 0; i < 4; ++i) aCur[i] = aNxt[i];
    }

    int mg0 = m0 + rA0;
    int mg1 = m0 + rA1;
#pragma unroll
    for (int j = 0; j < 16; ++j) {
        int col = j * 8 + 2 * tig;
        float ba = sBias[col], bb = sBias[col + 1];
        if (mg0 < N_NODES)
            *(float2*)(C + (size_t)mg0 * 384 + c0 + col) =
                make_float2(acc[j][0] + ba, acc[j][1] + bb);
        if (mg1 < N_NODES)
            *(float2*)(C + (size_t)mg1 * 384 + c0 + col) =
                make_float2(acc[j][2] + ba, acc[j][3] + bb);
    }
}

// ---------------- fused gh GEMM + GRU combine (+ agg zero for next layer) ----------------
// block = 32 rows x 384 cols (permuted); 8 warps = 2 row-groups x 4 col-groups
// warp cg holds cols {cg*32..+32} of each of r/z/n via the pn permutation
#define FB_STR 12
#define FA_H 0
#define FA_L 384
#define FB_OFF 768
#define FB_BUF (2 * 384 * FB_STR)
#define F_BIAS (FB_OFF + 2 * FB_BUF)
#define FUSE_SMEM ((F_BIAS + 384) * 4)

__global__ __launch_bounds__(256, 2)
void k_gru_fused(const float* __restrict__ bhh, int l) {
    extern __shared__ uint32_t smw[];
    uint32_t* sAh = smw + FA_H;   // [32][12]
    uint32_t* sAl = smw + FA_L;
    float* sBias = (float*)(smw + F_BIAS);
    const uint32_t su = smem_u32(smw);

    int tid = threadIdx.x;
    int w = tid >> 5, lane = tid & 31;
    int gid = lane >> 2, tig = lane & 3;
    int rg = w >> 2, cg = w & 3;

    const float* b = bhh + l * 3 * H;
    const uint32_t* wfh = g_WHF_hi + (size_t)l * 24576;
    const uint32_t* wfl = g_WHF_lo + (size_t)l * 24576;

    int m0 = blockIdx.x * 32;

    // issue B(0): chunk kc covers kw = kc*8..+8
    for (int p = tid; p < 384; p += 256) {
        uint32_t dh = su + (FB_OFF + p * FB_STR) * 4;
        cp16(dh, wfh + (size_t)p * 64);
        cp16(dh + 16, wfh + (size_t)p * 64 + 4);
        uint32_t dl = su + (FB_OFF + 384 * FB_STR + p * FB_STR) * 4;
        cp16(dl, wfl + (size_t)p * 64);
        cp16(dl + 16, wfl + (size_t)p * 64 + 4);
    }
    CP_COMMIT();

    for (int i = tid; i < 384; i += 256) sBias[i] = b[i];

    float acc[12][4];
#pragma unroll
    for (int j = 0; j < 12; ++j)
#pragma unroll
        for (int q = 0; q < 4; ++q) acc[j][q] = 0.f;

    int rA0 = rg * 16 + gid;
    int rA1 = rA0 + 8;

    // prefetch A(0): 32 rows x 16 k = 128 float4; threads 0..127
    float4 aCur, aNxt;
    int rL = tid >> 2, qL = tid & 3;
    if (tid < 128) {
        int m = m0 + rL;
        aCur = (m < N_NODES) ? *(const float4*)(g_h + (size_t)m * H + qL * 4)
                             : make_float4(0.f, 0.f, 0.f, 0.f);
    }

    for (int kc = 0; kc < 8; ++kc) {
        int buf = kc & 1;
        if (tid < 128) {
            uint32_t h0, l0, h1, l1;
            split_pack(aCur.x, aCur.y, h0, l0);
            split_pack(aCur.z, aCur.w, h1, l1);
            *(uint2*)(sAh + rL * FB_STR + qL * 2) = make_uint2(h0, h1);
            *(uint2*)(sAl + rL * FB_STR + qL * 2) = make_uint2(l0, l1);
        }
        if (kc < 7) {
            int kn = kc + 1;
            if (tid < 128) {
                int m = m0 + rL;
                aNxt = (m < N_NODES)
                    ? *(const float4*)(g_h + (size_t)m * H + kn * 16 + qL * 4)
                    : make_float4(0.f, 0.f, 0.f, 0.f);
            }
            int bo = FB_OFF + (buf ^ 1) * FB_BUF;
            for (int p = tid; p < 384; p += 256) {
                uint32_t dh = su + (bo + p * FB_STR) * 4;
                cp16(dh, wfh + (size_t)p * 64 + kn * 8);
                cp16(dh + 16, wfh + (size_t)p * 64 + kn * 8 + 4);
                uint32_t dl = su + (bo + 384 * FB_STR + p * FB_STR) * 4;
                cp16(dl, wfl + (size_t)p * 64 + kn * 8);
                cp16(dl + 16, wfl + (size_t)p * 64 + kn * 8 + 4);
            }
            CP_COMMIT();
            CP_WAIT1();
        } else {
            CP_WAIT0();
        }
        __syncthreads();
        const uint32_t* sBh = smw + FB_OFF + buf * FB_BUF;
        const uint32_t* sBl = sBh + 384 * FB_STR;
        uint32_t ah0 = sAh[rA0 * FB_STR + tig];
        uint32_t ah1 = sAh[rA1 * FB_STR + tig];
        uint32_t ah2 = sAh[rA0 * FB_STR + tig + 4];
        uint32_t ah3 = sAh[rA1 * FB_STR + tig + 4];
        uint32_t al0 = sAl[rA0 * FB_STR + tig];
        uint32_t al1 = sAl[rA1 * FB_STR + tig];
        uint32_t al2 = sAl[rA0 * FB_STR + tig + 4];
        uint32_t al3 = sAl[rA1 * FB_STR + tig + 4];
#pragma unroll
        for (int j = 0; j < 12; ++j) {
            int pn = cg * 96 + j * 8 + gid;
            uint32_t bh0 = sBh[pn * FB_STR + tig], bh1 = sBh[pn * FB_STR + tig + 4];
            uint32_t bl0 = sBl[pn * FB_STR + tig], bl1 = sBl[pn * FB_STR + tig + 4];
            mma_bf16(acc[j], ah0, ah1, ah2, ah3, bh0, bh1);
            mma_bf16(acc[j], al0, al1, al2, al3, bh0, bh1);
            mma_bf16(acc[j], ah0, ah1, ah2, ah3, bl0, bl1);
        }
        __syncthreads();
        aCur = aNxt;
    }

    // combine: acc[part*4+jj] holds gh for part(r=0,z=1,n=2), cols c = cg*32 + 8*jj + 2*tig + {0,1}
    int mg0 = m0 + rA0;
    int mg1 = m0 + rA1;
#pragma unroll
    for (int jj = 0; jj < 4; ++jj) {
        int c = cg * 32 + 8 * jj + 2 * tig;
        float br_ = sBias[c],       bz_ = sBias[128 + c],       bn_ = sBias[256 + c];
        float br1 = sBias[c + 1],   bz1 = sBias[128 + c + 1],   bn1 = sBias[256 + c + 1];
#pragma unroll
        for (int half = 0; half < 2; ++half) {
            int m = half ? mg1 : mg0;
            if (m >= N_NODES) continue;
            int q0 = half * 2;
            float ghr0 = acc[jj][q0] + br_,      ghr1 = acc[jj][q0 + 1] + br1;
            float ghz0 = acc[4 + jj][q0] + bz_,  ghz1 = acc[4 + jj][q0 + 1] + bz1;
            float ghn0 = acc[8 + jj][q0] + bn_,  ghn1 = acc[8 + jj][q0 + 1] + bn1;
            const float* gi = g_gi + (size_t)m * 384;
            float2 gir = *(const float2*)(gi + c);
            float2 giz = *(const float2*)(gi + 128 + c);
            float2 gin = *(const float2*)(gi + 256 + c);
            float2 hv = *(const float2*)(g_h + (size_t)m * H + c);
            float r0 = sigm(gir.x + ghr0), r1 = sigm(gir.y + ghr1);
            float z0 = sigm(giz.x + ghz0), z1 = sigm(giz.y + ghz1);
            float n0 = tanhf(gin.x + r0 * ghn0), n1 = tanhf(gin.y + r1 * ghn1);
            float2 hout = make_float2((1.f - z0) * n0 + z0 * hv.x,
                                      (1.f - z1) * n1 + z1 * hv.y);
            *(float2*)(g_h + (size_t)m * H + c) = hout;
            *(float2*)(g_agg + (size_t)m * H + c) = make_float2(0.f, 0.f);
        }
    }
}

// ---------------- readout ----------------
__global__ __launch_bounds__(256)
void k_readout(const float* __restrict__ Wr1, const float* __restrict__ br1,
               const float* __restrict__ Wr2, const float* __restrict__ br2,
               float* __restrict__ out, int nd) {
    extern __shared__ float smemf[];
    float* sW1 = smemf;
    float* sb1 = sW1 + H * H;
    float* sW2 = sb1 + H;
    float* sHrow = sW2 + H;

    for (int t = threadIdx.x; t < (H * H) / 4; t += blockDim.x)
        ((float4*)sW1)[t] = ((const float4*)Wr1)[t];
    if (threadIdx.x < H) {
        sb1[threadIdx.x] = br1[threadIdx.x];
        sW2[threadIdx.x] = Wr2[threadIdx.x];
    }
    __syncthreads();

    int w = threadIdx.x >> 5, lane = threadIdx.x & 31;
    float* myrow = sHrow + w * H;
    float b2v = br2[0];

    for (int n = blockIdx.x * 8 + w; n < nd; n += gridDim.x * 8) {
        ((float4*)myrow)[lane] = ((const float4*)(g_h + (size_t)n * H))[lane];
        __syncwarp();
        float hid0 = 0.f, hid1 = 0.f, hid2 = 0.f, hid3 = 0.f;
#pragma unroll 4
        for (int k = 0; k < H; ++k) {
            float a = myrow[k];
            float4 wv = ((const float4*)sW1)[k * 32 + lane];
            hid0 += a * wv.x; hid1 += a * wv.y; hid2 += a * wv.z; hid3 += a * wv.w;
        }
        float4 w2 = ((const float4*)sW2)[lane];
        float p = fmaxf(hid0 + sb1[lane * 4 + 0], 0.f) * w2.x
                + fmaxf(hid1 + sb1[lane * 4 + 1], 0.f) * w2.y
                + fmaxf(hid2 + sb1[lane * 4 + 2], 0.f) * w2.z
                + fmaxf(hid3 + sb1[lane * 4 + 3], 0.f) * w2.w;
#pragma unroll
        for (int o = 16; o > 0; o >>= 1) p += __shfl_down_sync(0xffffffffu, p, o);
        if (lane == 0) out[n] = p + b2v;
        __syncwarp();
    }
}

// ---------------- launch ----------------
extern "C" void kernel_launch(void* const* d_in, const int* in_sizes, int n_in,
                              void* d_out, int out_size) {
    int base = (n_in >= 18) ? 4 : 3;
    const float* x          = (const float*)d_in[0];
    const int*   edge_index = (const int*)d_in[1];
    const int*   edge_type  = (const int*)d_in[2];
    const float* W_in = (const float*)d_in[base + 0];
    const float* b_in = (const float*)d_in[base + 1];
    const float* W1   = (const float*)d_in[base + 2];
    const float* b1   = (const float*)d_in[base + 3];
    const float* W2   = (const float*)d_in[base + 4];
    const float* b2   = (const float*)d_in[base + 5];
    const float* W_ih = (const float*)d_in[base + 6];
    const float* b_ih = (const float*)d_in[base + 7];
    const float* W_hh = (const float*)d_in[base + 8];
    const float* b_hh = (const float*)d_in[base + 9];
    const float* Wr1  = (const float*)d_in[base + 10];
    const float* br1  = (const float*)d_in[base + 11];
    const float* Wr2  = (const float*)d_in[base + 12];
    const float* br2  = (const float*)d_in[base + 13];
    float* out = (float*)d_out;

    const int READ_SMEM = (128 * 128 + 128 + 128 + 8 * 128) * 4;
    cudaFuncSetAttribute(k_edge_tc,   cudaFuncAttributeMaxDynamicSharedMemorySize, EDGE_SMEM);
    cudaFuncSetAttribute(k_gru_gi,    cudaFuncAttributeMaxDynamicSharedMemorySize, GRU_SMEM);
    cudaFuncSetAttribute(k_gru_fused, cudaFuncAttributeMaxDynamicSharedMemorySize, FUSE_SMEM);
    cudaFuncSetAttribute(k_readout,   cudaFuncAttributeMaxDynamicSharedMemorySize, READ_SMEM);

    k_zero_cnt<<<1, 32>>>();
    k_count<<<(N_EDGESC + 255) / 256, 256>>>(edge_type);
    k_seed<<<1, 1>>>();
    k_scatter<<<(N_EDGESC + 255) / 256, 256>>>(edge_type);

    const int NPW = 6 * 128 * 128 + 6 * 128 * 64;
    k_prep_w<<<(NPW + 255) / 256, 256>>>(W1, W2);
    k_prep_gru<<<(2 * 3 * 384 * 64 + 255) / 256, 256>>>(W_ih, W_hh);
    k_init<<<(N_NODES * H + 255) / 256, 256>>>(x, W_in, b_in);

    const int EDGE_BLOCKS = N_EDGESC / TILE_E + 2;
    for (int l = 0; l < 3; ++l) {
        k_edge_tc<<<EDGE_BLOCKS, 256, EDGE_SMEM>>>(edge_index, b1, b2, l);
        dim3 gg((N_NODES + 127) / 128, 3, 1);
        k_gru_gi<<<gg, 256, GRU_SMEM>>>(b_ih, l);
        k_gru_fused<<<(N_NODES + 31) / 32, 256, FUSE_SMEM>>>(b_hh, l);
    }

    k_readout<<<625, 256, READ_SMEM>>>(Wr1, br1, Wr2, br2, out, out_size);
}

// round 15
// speedup vs baseline: 1.2223x; 1.2223x over previous
#include <cuda_runtime.h>
#include <cuda_bf16.h>
#include <math.h>
#include <stdint.h>

#define N_NODES 50000
#define N_EDGESC 400000
#define H 128
#define NT 2
#define FEAT 4
#define TILE_E 128

// ---------------- device scratch (no runtime allocation) ----------------
__device__ float g_h[N_NODES * H];
__device__ float g_agg[N_NODES * H];
__device__ float g_gi[N_NODES * 3 * H];
__device__ float g_gh[N_NODES * 3 * H];
__device__ float g_P1[2 * N_NODES * H];   // h @ W1_top per type
__device__ float g_P2[2 * N_NODES * H];   // h @ W1_bot per type
__device__ int   g_perm[N_EDGESC];
__device__ int   g_cnt[2];
__device__ int   g_cursor[2];
// W1 node-GEMM layout: [lt][half][n(128)][kw(64)] bf16x2 hi/lo
__device__ uint32_t g_WPB_hi[6 * 2 * 128 * 64];
__device__ uint32_t g_WPB_lo[6 * 2 * 128 * 64];
// W2 edge layout: [lt][n(128)][kw(64)]
__device__ uint32_t g_W2B_hi[6 * 128 * 64];
__device__ uint32_t g_W2B_lo[6 * 128 * 64];
// GRU weights: [sel(ih/hh)][l][n(384)][kw(64)]
__device__ uint32_t g_WGB_hi[2 * 3 * 384 * 64];
__device__ uint32_t g_WGB_lo[2 * 3 * 384 * 64];

__device__ __forceinline__ float sigm(float v) { return 1.0f / (1.0f + expf(-v)); }

__device__ __forceinline__ void split_pack(float x, float y, uint32_t& hi, uint32_t& lo) {
    __nv_bfloat162 h = __floats2bfloat162_rn(x, y);
    hi = reinterpret_cast<uint32_t&>(h);
    float rx = x - __low2float(h);
    float ry = y - __high2float(h);
    __nv_bfloat162 l = __floats2bfloat162_rn(rx, ry);
    lo = reinterpret_cast<uint32_t&>(l);
}

__device__ __forceinline__ void mma_bf16(float* c, uint32_t a0, uint32_t a1, uint32_t a2,
                                         uint32_t a3, uint32_t b0, uint32_t b1) {
    asm volatile(
        "mma.sync.aligned.m16n8k16.row.col.f32.bf16.bf16.f32 "
        "{%0,%1,%2,%3}, {%4,%5,%6,%7}, {%8,%9}, {%0,%1,%2,%3};"
        : "+f"(c[0]), "+f"(c[1]), "+f"(c[2]), "+f"(c[3])
        : "r"(a0), "r"(a1), "r"(a2), "r"(a3), "r"(b0), "r"(b1));
}

__device__ __forceinline__ void red2(float* p, float a, float b) {
    asm volatile("red.global.add.v2.f32 [%0], {%1, %2};" :: "l"(p), "f"(a), "f"(b) : "memory");
}

__device__ __forceinline__ void cp16(uint32_t saddr, const void* g) {
    asm volatile("cp.async.cg.shared.global [%0], [%1], 16;" :: "r"(saddr), "l"(g));
}
#define CP_COMMIT() asm volatile("cp.async.commit_group;" ::: "memory")
#define CP_WAIT0()  asm volatile("cp.async.wait_group 0;" ::: "memory")
#define CP_WAIT1()  asm volatile("cp.async.wait_group 1;" ::: "memory")

__device__ __forceinline__ uint32_t smem_u32(const void* p) {
    uint32_t a;
    asm("{ .reg .u64 t; cvta.to.shared.u64 t, %1; cvt.u32.u64 %0, t; }" : "=r"(a) : "l"(p));
    return a;
}

// ---------------- edge partition by type ----------------
__global__ void k_zero_cnt() { if (threadIdx.x < 2) g_cnt[threadIdx.x] = 0; }

__global__ void k_count(const int* __restrict__ et) {
    __shared__ int lc[2];
    if (threadIdx.x < 2) lc[threadIdx.x] = 0;
    __syncthreads();
    int e = blockIdx.x * blockDim.x + threadIdx.x;
    if (e < N_EDGESC) atomicAdd(&lc[et[e]], 1);
    __syncthreads();
    if (threadIdx.x < 2) atomicAdd(&g_cnt[threadIdx.x], lc[threadIdx.x]);
}

__global__ void k_seed() { g_cursor[0] = 0; g_cursor[1] = g_cnt[0]; }

__global__ void k_scatter(const int* __restrict__ et) {
    __shared__ int lc[2];
    __shared__ int base[2];
    if (threadIdx.x < 2) lc[threadIdx.x] = 0;
    __syncthreads();
    int e = blockIdx.x * blockDim.x + threadIdx.x;
    int t = 0, rank = 0;
    bool valid = (e < N_EDGESC);
    if (valid) { t = et[e]; rank = atomicAdd(&lc[t], 1); }
    __syncthreads();
    if (threadIdx.x < 2) base[threadIdx.x] = atomicAdd(&g_cursor[threadIdx.x], lc[threadIdx.x]);
    __syncthreads();
    if (valid) g_perm[base[t] + rank] = e;
}

// ---------------- weight prep ----------------
__global__ void k_prep_w(const float* __restrict__ W1, const float* __restrict__ W2) {
    int idx = blockIdx.x * blockDim.x + threadIdx.x;
    const int NW1 = 6 * 2 * 128 * 64;   // node layout words
    const int NW2 = 6 * 128 * 64;
    if (idx < NW1) {
        int lt = idx >> 14, rem = idx & 16383;
        int half = rem >> 13, rem2 = rem & 8191;
        int n = rem2 >> 6, kw = rem2 & 63;
        const float* base = W1 + (size_t)lt * 32768;
        int k = half * 128 + 2 * kw;
        float v0 = base[(size_t)k * 128 + n];
        float v1 = base[(size_t)(k + 1) * 128 + n];
        uint32_t hi, lo;
        split_pack(v0, v1, hi, lo);
        g_WPB_hi[idx] = hi; g_WPB_lo[idx] = lo;
    } else if (idx < NW1 + NW2) {
        int i2 = idx - NW1;
        int lt = i2 >> 13, rem = i2 & 8191;
        int n = rem >> 6, kw = rem & 63;
        const float* base = W2 + (size_t)lt * 16384;
        float v0 = base[(2 * kw) * 128 + n];
        float v1 = base[(2 * kw + 1) * 128 + n];
        uint32_t hi, lo;
        split_pack(v0, v1, hi, lo);
        int o = lt * 8192 + n * 64 + kw;
        g_W2B_hi[o] = hi; g_W2B_lo[o] = lo;
    }
}

__global__ void k_prep_gru(const float* __restrict__ Wih, const float* __restrict__ Whh) {
    int idx = blockIdx.x * blockDim.x + threadIdx.x;
    const int TOT = 2 * 3 * 384 * 64;
    if (idx >= TOT) return;
    int sel = idx / 73728, rem = idx % 73728;
    int l = rem / 24576, rem2 = rem % 24576;
    int n = rem2 >> 6, kw = rem2 & 63;
    const float* src = (sel ? Whh : Wih) + (size_t)l * H * 3 * H;
    float v0 = src[(2 * kw) * 384 + n];
    float v1 = src[(2 * kw + 1) * 384 + n];
    uint32_t hi, lo;
    split_pack(v0, v1, hi, lo);
    g_WGB_hi[idx] = hi;
    g_WGB_lo[idx] = lo;
}

// ---------------- h = relu(x @ W_in + b_in); zero agg for layer 0 ----------------
__global__ void k_init(const float* __restrict__ x, const float* __restrict__ Win,
                       const float* __restrict__ bin) {
    __shared__ float sW[FEAT * H];
    __shared__ float sb[H];
    for (int i = threadIdx.x; i < FEAT * H; i += blockDim.x) sW[i] = Win[i];
    if (threadIdx.x < H) sb[threadIdx.x] = bin[threadIdx.x];
    __syncthreads();
    int idx = blockIdx.x * blockDim.x + threadIdx.x;
    if (idx >= N_NODES * H) return;
    int n = idx >> 7, c = idx & 127;
    float4 xr = ((const float4*)x)[n];
    float v = sb[c] + xr.x * sW[c] + xr.y * sW[H + c] + xr.z * sW[2 * H + c] + xr.w * sW[3 * H + c];
    g_h[idx] = fmaxf(v, 0.0f);
    g_agg[idx] = 0.0f;
}

// ---------------- shared pipeline constants ----------------
#define A_STR 68
#define B_STR 20
#define F_AH 0
#define F_AL (128 * A_STR)
#define F_B  (2 * 128 * A_STR)
#define B_BUF_W (2 * 128 * B_STR)
#define F_META (F_B + 2 * B_BUF_W)
#define EDGE_SMEM ((F_META + 512) * 4)

#define A2_STR 20
#define G_AH 0
#define G_AL (128 * A2_STR)
#define G_B  (2 * 128 * A2_STR)
#define GB_BUF_W (2 * 128 * B_STR)
#define G_BIAS (G_B + 2 * GB_BUF_W)
#define GRU_SMEM ((G_BIAS + 128) * 4)

// ---------------- node precompute: P1/P2 = h @ W1_{top,bot} per type ----------------
__global__ __launch_bounds__(256, 2)
void k_node_pre(int l) {
    extern __shared__ uint32_t smw[];
    uint32_t* sAh = smw + G_AH;
    uint32_t* sAl = smw + G_AL;
    const uint32_t su = smem_u32(smw);

    int tid = threadIdx.x;
    int w = tid >> 5, lane = tid & 31;
    int gid = lane >> 2, tig = lane & 3;

    int t = blockIdx.y >> 1, half = blockIdx.y & 1;
    const uint32_t* wbh = g_WPB_hi + ((size_t)(l * NT + t) * 2 + half) * 8192;
    const uint32_t* wbl = g_WPB_lo + ((size_t)(l * NT + t) * 2 + half) * 8192;
    float* C = (half ? g_P2 : g_P1) + (size_t)t * N_NODES * H;

    int m0 = blockIdx.x * 128;
    int nB = tid >> 1, offB = (tid & 1) * 8;

    {
        uint32_t dst = su + (G_B + nB * B_STR + offB) * 4;
        const uint32_t* gh_ = wbh + (size_t)nB * 64 + offB;
        const uint32_t* gl_ = wbl + (size_t)nB * 64 + offB;
        cp16(dst, gh_); cp16(dst + 16, gh_ + 4);
        cp16(dst + 128 * B_STR * 4, gl_); cp16(dst + 128 * B_STR * 4 + 16, gl_ + 4);
        CP_COMMIT();
    }

    float acc[16][4];
#pragma unroll
    for (int j = 0; j < 16; ++j)
#pragma unroll
        for (int q = 0; q < 4; ++q) acc[j][q] = 0.f;

    int rA0 = w * 16 + gid;
    int rA1 = rA0 + 8;

    float4 aCur[4], aNxt[4];
#pragma unroll
    for (int i = 0; i < 4; ++i) {
        int i0 = tid + i * 256, r = i0 >> 3, q = i0 & 7;
        int m = m0 + r;
        aCur[i] = (m < N_NODES) ? *(const float4*)(g_h + (size_t)m * H + q * 4)
                                : make_float4(0.f, 0.f, 0.f, 0.f);
    }

    for (int kc = 0; kc < 4; ++kc) {
        int buf = kc & 1;
#pragma unroll
        for (int i = 0; i < 4; ++i) {
            int i0 = tid + i * 256, r = i0 >> 3, q = i0 & 7;
            uint32_t h0, l0, h1, l1;
            split_pack(aCur[i].x, aCur[i].y, h0, l0);
            split_pack(aCur[i].z, aCur[i].w, h1, l1);
            *(uint2*)(sAh + r * A2_STR + q * 2) = make_uint2(h0, h1);
            *(uint2*)(sAl + r * A2_STR + q * 2) = make_uint2(l0, l1);
        }
        if (kc < 3) {
            int kn = kc + 1;
#pragma unroll
            for (int i = 0; i < 4; ++i) {
                int i0 = tid + i * 256, r = i0 >> 3, q = i0 & 7;
                int m = m0 + r;
                aNxt[i] = (m < N_NODES)
                    ? *(const float4*)(g_h + (size_t)m * H + kn * 32 + q * 4)
                    : make_float4(0.f, 0.f, 0.f, 0.f);
            }
            uint32_t dst = su + (G_B + (buf ^ 1) * GB_BUF_W + nB * B_STR + offB) * 4;
            const uint32_t* gh_ = wbh + (size_t)nB * 64 + kn * 16 + offB;
            const uint32_t* gl_ = wbl + (size_t)nB * 64 + kn * 16 + offB;
            cp16(dst, gh_); cp16(dst + 16, gh_ + 4);
            cp16(dst + 128 * B_STR * 4, gl_); cp16(dst + 128 * B_STR * 4 + 16, gl_ + 4);
            CP_COMMIT();
            CP_WAIT1();
        } else {
            CP_WAIT0();
        }
        __syncthreads();
        const uint32_t* sBh = smw + G_B + buf * GB_BUF_W;
        const uint32_t* sBl = sBh + 128 * B_STR;
#pragma unroll
        for (int s = 0; s < 2; ++s) {
            int kwb = 8 * s;
            uint32_t ah0 = sAh[rA0 * A2_STR + kwb + tig];
            uint32_t ah1 = sAh[rA1 * A2_STR + kwb + tig];
            uint32_t ah2 = sAh[rA0 * A2_STR + kwb + tig + 4];
            uint32_t ah3 = sAh[rA1 * A2_STR + kwb + tig + 4];
            uint32_t al0 = sAl[rA0 * A2_STR + kwb + tig];
            uint32_t al1 = sAl[rA1 * A2_STR + kwb + tig];
            uint32_t al2 = sAl[rA0 * A2_STR + kwb + tig + 4];
            uint32_t al3 = sAl[rA1 * A2_STR + kwb + tig + 4];
#pragma unroll
            for (int j = 0; j < 16; ++j) {
                int nb = (j * 8 + gid) * B_STR + kwb + tig;
                uint32_t bh0 = sBh[nb], bh1 = sBh[nb + 4];
                uint32_t bl0 = sBl[nb], bl1 = sBl[nb + 4];
                mma_bf16(acc[j], ah0, ah1, ah2, ah3, bh0, bh1);
                mma_bf16(acc[j], al0, al1, al2, al3, bh0, bh1);
                mma_bf16(acc[j], ah0, ah1, ah2, ah3, bl0, bl1);
            }
        }
        __syncthreads();
#pragma unroll
        for (int i = 0; i < 4; ++i) aCur[i] = aNxt[i];
    }

    int mg0 = m0 + rA0;
    int mg1 = m0 + rA1;
#pragma unroll
    for (int j = 0; j < 16; ++j) {
        int col = j * 8 + 2 * tig;
        if (mg0 < N_NODES)
            *(float2*)(C + (size_t)mg0 * H + col) = make_float2(acc[j][0], acc[j][1]);
        if (mg1 < N_NODES)
            *(float2*)(C + (size_t)mg1 * H + col) = make_float2(acc[j][2], acc[j][3]);
    }
}

// ---------------- edge kernel: gather hidden from P1/P2, GEMM2 only ----------------
__global__ __launch_bounds__(256, 2)
void k_edge_tc(const int* __restrict__ edge_index,
               const float* __restrict__ b1, const float* __restrict__ b2, int l) {
    extern __shared__ uint32_t smw[];
    uint32_t* sAh = smw + F_AH;
    uint32_t* sAl = smw + F_AL;
    int*   sSrc = (int*)(smw + F_META);
    int*   sDst = sSrc + 128;
    float* sB1  = (float*)(sDst + 128);
    float* sB2  = sB1 + 128;
    const uint32_t su = smem_u32(smw);

    int tid = threadIdx.x;
    int w = tid >> 5, lane = tid & 31;
    int gid = lane >> 2, tig = lane & 3;

    int cnt0 = g_cnt[0];
    int nb0 = (cnt0 + TILE_E - 1) / TILE_E;
    int type, start, cnt, permBase;
    if ((int)blockIdx.x < nb0) {
        type = 0; start = blockIdx.x * TILE_E; cnt = cnt0; permBase = 0;
    } else {
        type = 1; start = ((int)blockIdx.x - nb0) * TILE_E;
        cnt = N_EDGESC - cnt0; permBase = cnt0;
        if (start >= cnt) return;
    }
    int lt = l * NT + type;

    const uint32_t* w2h = g_W2B_hi + (size_t)lt * 8192;
    const uint32_t* w2l = g_W2B_lo + (size_t)lt * 8192;
    const float* P1t = g_P1 + (size_t)type * N_NODES * H;
    const float* P2t = g_P2 + (size_t)type * N_NODES * H;

    int nB = tid >> 1, offB = (tid & 1) * 8;

    // issue B2(0) into buf 0
    {
        uint32_t dst = su + (F_B + nB * B_STR + offB) * 4;
        const uint32_t* gh_ = w2h + nB * 64 + offB;
        const uint32_t* gl_ = w2l + nB * 64 + offB;
        cp16(dst, gh_); cp16(dst + 16, gh_ + 4);
        cp16(dst + 128 * B_STR * 4, gl_); cp16(dst + 128 * B_STR * 4 + 16, gl_ + 4);
        CP_COMMIT();
    }

    if (tid < 128) {
        int g = start + tid; int s = -1, d = -1;
        if (g < cnt) { int e = g_perm[permBase + g]; s = edge_index[e]; d = edge_index[N_EDGESC + e]; }
        sSrc[tid] = s;
        sDst[tid] = d;
    } else {
        int c = tid - 128;
        sB1[c] = b1[lt * H + c];
        sB2[c] = b2[lt * H + c];
    }
    __syncthreads();

    // gather hidden = relu(P1[src] + P2[dst] + b1), split-pack into sAh/sAl kw 0..63
    for (int i = tid; i < 128 * 32; i += 256) {
        int r = i >> 5, c4 = i & 31;
        int s = sSrc[r], d = sDst[r];
        float4 hv = make_float4(0.f, 0.f, 0.f, 0.f);
        if (s >= 0) {
            float4 v1 = *(const float4*)(P1t + (size_t)s * H + c4 * 4);
            float4 v2 = *(const float4*)(P2t + (size_t)d * H + c4 * 4);
            float4 bb = *(const float4*)(sB1 + c4 * 4);
            hv.x = fmaxf(v1.x + v2.x + bb.x, 0.f);
            hv.y = fmaxf(v1.y + v2.y + bb.y, 0.f);
            hv.z = fmaxf(v1.z + v2.z + bb.z, 0.f);
            hv.w = fmaxf(v1.w + v2.w + bb.w, 0.f);
        }
        uint32_t h0, l0, h1, l1;
        split_pack(hv.x, hv.y, h0, l0);
        split_pack(hv.z, hv.w, h1, l1);
        *(uint2*)(sAh + r * A_STR + c4 * 2) = make_uint2(h0, h1);
        *(uint2*)(sAl + r * A_STR + c4 * 2) = make_uint2(l0, l1);
    }

    float acc[16][4];
#pragma unroll
    for (int j = 0; j < 16; ++j)
#pragma unroll
        for (int q = 0; q < 4; ++q) acc[j][q] = 0.f;

    int rA0 = w * 16 + gid;
    int rA1 = rA0 + 8;

    // GEMM2: 4 K-chunks, pipelined B
    for (int kc = 0; kc < 4; ++kc) {
        int buf = kc & 1;
        if (kc < 3) {
            int kn = kc + 1;
            uint32_t dst = su + (F_B + (buf ^ 1) * B_BUF_W + nB * B_STR + offB) * 4;
            const uint32_t* gh_ = w2h + nB * 64 + kn * 16 + offB;
            const uint32_t* gl_ = w2l + nB * 64 + kn * 16 + offB;
            cp16(dst, gh_); cp16(dst + 16, gh_ + 4);
            cp16(dst + 128 * B_STR * 4, gl_); cp16(dst + 128 * B_STR * 4 + 16, gl_ + 4);
            CP_COMMIT();
            CP_WAIT1();
        } else {
            CP_WAIT0();
        }
        __syncthreads();
        const uint32_t* sBh = smw + F_B + buf * B_BUF_W;
        const uint32_t* sBl = sBh + 128 * B_STR;
#pragma unroll
        for (int s = 0; s < 2; ++s) {
            int kwb = kc * 16 + 8 * s;
            uint32_t ah0 = sAh[rA0 * A_STR + kwb + tig];
            uint32_t ah1 = sAh[rA1 * A_STR + kwb + tig];
            uint32_t ah2 = sAh[rA0 * A_STR + kwb + tig + 4];
            uint32_t ah3 = sAh[rA1 * A_STR + kwb + tig + 4];
            uint32_t al0 = sAl[rA0 * A_STR + kwb + tig];
            uint32_t al1 = sAl[rA1 * A_STR + kwb + tig];
            uint32_t al2 = sAl[rA0 * A_STR + kwb + tig + 4];
            uint32_t al3 = sAl[rA1 * A_STR + kwb + tig + 4];
#pragma unroll
            for (int j = 0; j < 16; ++j) {
                int nb = (j * 8 + gid) * B_STR + 8 * s + tig;
                uint32_t bh0 = sBh[nb], bh1 = sBh[nb + 4];
                uint32_t bl0 = sBl[nb], bl1 = sBl[nb + 4];
                mma_bf16(acc[j], ah0, ah1, ah2, ah3, bh0, bh1);
                mma_bf16(acc[j], al0, al1, al2, al3, bh0, bh1);
                mma_bf16(acc[j], ah0, ah1, ah2, ah3, bl0, bl1);
            }
        }
        __syncthreads();
    }

    // epilogue: msgs = acc + b2 -> red into agg[dst]
    int d0 = sDst[rA0];
    int d1 = sDst[rA1];
#pragma unroll
    for (int j = 0; j < 16; ++j) {
        int col = j * 8 + 2 * tig;
        float ba = sB2[col], bb = sB2[col + 1];
        if (d0 >= 0) red2(g_agg + (size_t)d0 * H + col, acc[j][0] + ba, acc[j][1] + bb);
        if (d1 >= 0) red2(g_agg + (size_t)d1 * H + col, acc[j][2] + ba, acc[j][3] + bb);
    }
}

// ---------------- GRU GEMMs (R13 proven version) ----------------
__global__ __launch_bounds__(256, 2)
void k_gru_tc(const float* __restrict__ bih, const float* __restrict__ bhh, int l) {
    extern __shared__ uint32_t smw[];
    uint32_t* sAh = smw + G_AH;
    uint32_t* sAl = smw + G_AL;
    float* sBias = (float*)(smw + G_BIAS);
    const uint32_t su = smem_u32(smw);

    int tid = threadIdx.x;
    int w = tid >> 5, lane = tid & 31;
    int gid = lane >> 2, tig = lane & 3;

    int sel = blockIdx.z;
    const float* A = sel ? g_h : g_agg;
    float* C = sel ? g_gh : g_gi;
    const float* b = (sel ? bhh : bih) + l * 3 * H;
    const uint32_t* wbh = g_WGB_hi + ((size_t)sel * 3 + l) * 384 * 64;
    const uint32_t* wbl = g_WGB_lo + ((size_t)sel * 3 + l) * 384 * 64;

    int m0 = blockIdx.x * 128;
    int c0 = blockIdx.y * 128;

    int nB = tid >> 1, offB = (tid & 1) * 8;

    {
        uint32_t dst = su + (G_B + nB * B_STR + offB) * 4;
        const uint32_t* gh_ = wbh + (size_t)(c0 + nB) * 64 + offB;
        const uint32_t* gl_ = wbl + (size_t)(c0 + nB) * 64 + offB;
        cp16(dst, gh_); cp16(dst + 16, gh_ + 4);
        cp16(dst + 128 * B_STR * 4, gl_); cp16(dst + 128 * B_STR * 4 + 16, gl_ + 4);
        CP_COMMIT();
    }

    if (tid < 128) sBias[tid] = b[c0 + tid];

    float acc[16][4];
#pragma unroll
    for (int j = 0; j < 16; ++j)
#pragma unroll
        for (int q = 0; q < 4; ++q) acc[j][q] = 0.f;

    int rA0 = w * 16 + gid;
    int rA1 = rA0 + 8;

    float4 aCur[4], aNxt[4];
#pragma unroll
    for (int i = 0; i < 4; ++i) {
        int i0 = tid + i * 256, r = i0 >> 3, q = i0 & 7;
        int m = m0 + r;
        aCur[i] = (m < N_NODES) ? *(const float4*)(A + (size_t)m * H + q * 4)
                                : make_float4(0.f, 0.f, 0.f, 0.f);
    }

    for (int kc = 0; kc < 4; ++kc) {
        int buf = kc & 1;
#pragma unroll
        for (int i = 0; i < 4; ++i) {
            int i0 = tid + i * 256, r = i0 >> 3, q = i0 & 7;
            uint32_t h0, l0, h1, l1;
            split_pack(aCur[i].x, aCur[i].y, h0, l0);
            split_pack(aCur[i].z, aCur[i].w, h1, l1);
            *(uint2*)(sAh + r * A2_STR + q * 2) = make_uint2(h0, h1);
            *(uint2*)(sAl + r * A2_STR + q * 2) = make_uint2(l0, l1);
        }
        if (kc < 3) {
            int kn = kc + 1;
#pragma unroll
            for (int i = 0; i < 4; ++i) {
                int i0 = tid + i * 256, r = i0 >> 3, q = i0 & 7;
                int m = m0 + r;
                aNxt[i] = (m < N_NODES)
                    ? *(const float4*)(A + (size_t)m * H + kn * 32 + q * 4)
                    : make_float4(0.f, 0.f, 0.f, 0.f);
            }
            uint32_t dst = su + (G_B + (buf ^ 1) * GB_BUF_W + nB * B_STR + offB) * 4;
            const uint32_t* gh_ = wbh + (size_t)(c0 + nB) * 64 + kn * 16 + offB;
            const uint32_t* gl_ = wbl + (size_t)(c0 + nB) * 64 + kn * 16 + offB;
            cp16(dst, gh_); cp16(dst + 16, gh_ + 4);
            cp16(dst + 128 * B_STR * 4, gl_); cp16(dst + 128 * B_STR * 4 + 16, gl_ + 4);
            CP_COMMIT();
            CP_WAIT1();
        } else {
            CP_WAIT0();
        }
        __syncthreads();
        const uint32_t* sBh = smw + G_B + buf * GB_BUF_W;
        const uint32_t* sBl = sBh + 128 * B_STR;
#pragma unroll
        for (int s = 0; s < 2; ++s) {
            int kwb = 8 * s;
            uint32_t ah0 = sAh[rA0 * A2_STR + kwb + tig];
            uint32_t ah1 = sAh[rA1 * A2_STR + kwb + tig];
            uint32_t ah2 = sAh[rA0 * A2_STR + kwb + tig + 4];
            uint32_t ah3 = sAh[rA1 * A2_STR + kwb + tig + 4];
            uint32_t al0 = sAl[rA0 * A2_STR + kwb + tig];
            uint32_t al1 = sAl[rA1 * A2_STR + kwb + tig];
            uint32_t al2 = sAl[rA0 * A2_STR + kwb + tig + 4];
            uint32_t al3 = sAl[rA1 * A2_STR + kwb + tig + 4];
#pragma unroll
            for (int j = 0; j < 16; ++j) {
                int nb = (j * 8 + gid) * B_STR + kwb + tig;
                uint32_t bh0 = sBh[nb], bh1 = sBh[nb + 4];
                uint32_t bl0 = sBl[nb], bl1 = sBl[nb + 4];
                mma_bf16(acc[j], ah0, ah1, ah2, ah3, bh0, bh1);
                mma_bf16(acc[j], al0, al1, al2, al3, bh0, bh1);
                mma_bf16(acc[j], ah0, ah1, ah2, ah3, bl0, bl1);
            }
        }
        __syncthreads();
#pragma unroll
        for (int i = 0; i < 4; ++i) aCur[i] = aNxt[i];
    }

    int mg0 = m0 + rA0;
    int mg1 = m0 + rA1;
#pragma unroll
    for (int j = 0; j < 16; ++j) {
        int col = j * 8 + 2 * tig;
        float ba = sBias[col], bb = sBias[col + 1];
        if (mg0 < N_NODES)
            *(float2*)(C + (size_t)mg0 * 384 + c0 + col) =
                make_float2(acc[j][0] + ba, acc[j][1] + bb);
        if (mg1 < N_NODES)
            *(float2*)(C + (size_t)mg1 * 384 + c0 + col) =
                make_float2(acc[j][2] + ba, acc[j][3] + bb);
    }
}

__global__ void k_gru_combine() {
    int idx = blockIdx.x * blockDim.x + threadIdx.x;
    if (idx >= N_NODES * H) return;
    int n = idx >> 7, c = idx & 127;
    const float* gi = g_gi + (size_t)n * 384;
    const float* gh = g_gh + (size_t)n * 384;
    float r = sigm(gi[c] + gh[c]);
    float z = sigm(gi[128 + c] + gh[128 + c]);
    float nn = tanhf(gi[256 + c] + r * gh[256 + c]);
    g_h[idx] = (1.0f - z) * nn + z * g_h[idx];
    g_agg[idx] = 0.0f;   // ready for next layer's edge scatter
}

// ---------------- readout ----------------
__global__ __launch_bounds__(256)
void k_readout(const float* __restrict__ Wr1, const float* __restrict__ br1,
               const float* __restrict__ Wr2, const float* __restrict__ br2,
               float* __restrict__ out, int nd) {
    extern __shared__ float smemf[];
    float* sW1 = smemf;
    float* sb1 = sW1 + H * H;
    float* sW2 = sb1 + H;
    float* sHrow = sW2 + H;

    for (int t = threadIdx.x; t < (H * H) / 4; t += blockDim.x)
        ((float4*)sW1)[t] = ((const float4*)Wr1)[t];
    if (threadIdx.x < H) {
        sb1[threadIdx.x] = br1[threadIdx.x];
        sW2[threadIdx.x] = Wr2[threadIdx.x];
    }
    __syncthreads();

    int w = threadIdx.x >> 5, lane = threadIdx.x & 31;
    float* myrow = sHrow + w * H;
    float b2v = br2[0];

    for (int n = blockIdx.x * 8 + w; n < nd; n += gridDim.x * 8) {
        ((float4*)myrow)[lane] = ((const float4*)(g_h + (size_t)n * H))[lane];
        __syncwarp();
        float hid0 = 0.f, hid1 = 0.f, hid2 = 0.f, hid3 = 0.f;
#pragma unroll 4
        for (int k = 0; k < H; ++k) {
            float a = myrow[k];
            float4 wv = ((const float4*)sW1)[k * 32 + lane];
            hid0 += a * wv.x; hid1 += a * wv.y; hid2 += a * wv.z; hid3 += a * wv.w;
        }
        float4 w2 = ((const float4*)sW2)[lane];
        float p = fmaxf(hid0 + sb1[lane * 4 + 0], 0.f) * w2.x
                + fmaxf(hid1 + sb1[lane * 4 + 1], 0.f) * w2.y
                + fmaxf(hid2 + sb1[lane * 4 + 2], 0.f) * w2.z
                + fmaxf(hid3 + sb1[lane * 4 + 3], 0.f) * w2.w;
#pragma unroll
        for (int o = 16; o > 0; o >>= 1) p += __shfl_down_sync(0xffffffffu, p, o);
        if (lane == 0) out[n] = p + b2v;
        __syncwarp();
    }
}

// ---------------- launch ----------------
extern "C" void kernel_launch(void* const* d_in, const int* in_sizes, int n_in,
                              void* d_out, int out_size) {
    int base = (n_in >= 18) ? 4 : 3;
    const float* x          = (const float*)d_in[0];
    const int*   edge_index = (const int*)d_in[1];
    const int*   edge_type  = (const int*)d_in[2];
    const float* W_in = (const float*)d_in[base + 0];
    const float* b_in = (const float*)d_in[base + 1];
    const float* W1   = (const float*)d_in[base + 2];
    const float* b1   = (const float*)d_in[base + 3];
    const float* W2   = (const float*)d_in[base + 4];
    const float* b2   = (const float*)d_in[base + 5];
    const float* W_ih = (const float*)d_in[base + 6];
    const float* b_ih = (const float*)d_in[base + 7];
    const float* W_hh = (const float*)d_in[base + 8];
    const float* b_hh = (const float*)d_in[base + 9];
    const float* Wr1  = (const float*)d_in[base + 10];
    const float* br1  = (const float*)d_in[base + 11];
    const float* Wr2  = (const float*)d_in[base + 12];
    const float* br2  = (const float*)d_in[base + 13];
    float* out = (float*)d_out;

    const int READ_SMEM = (128 * 128 + 128 + 128 + 8 * 128) * 4;
    cudaFuncSetAttribute(k_edge_tc,  cudaFuncAttributeMaxDynamicSharedMemorySize, EDGE_SMEM);
    cudaFuncSetAttribute(k_node_pre, cudaFuncAttributeMaxDynamicSharedMemorySize, GRU_SMEM);
    cudaFuncSetAttribute(k_gru_tc,   cudaFuncAttributeMaxDynamicSharedMemorySize, GRU_SMEM);
    cudaFuncSetAttribute(k_readout,  cudaFuncAttributeMaxDynamicSharedMemorySize, READ_SMEM);

    k_zero_cnt<<<1, 32>>>();
    k_count<<<(N_EDGESC + 255) / 256, 256>>>(edge_type);
    k_seed<<<1, 1>>>();
    k_scatter<<<(N_EDGESC + 255) / 256, 256>>>(edge_type);

    const int NPW = 6 * 2 * 128 * 64 + 6 * 128 * 64;
    k_prep_w<<<(NPW + 255) / 256, 256>>>(W1, W2);
    k_prep_gru<<<(2 * 3 * 384 * 64 + 255) / 256, 256>>>(W_ih, W_hh);
    k_init<<<(N_NODES * H + 255) / 256, 256>>>(x, W_in, b_in);

    const int NEL = N_NODES * H;
    const int EDGE_BLOCKS = N_EDGESC / TILE_E + 2;
    for (int l = 0; l < 3; ++l) {
        dim3 gp((N_NODES + 127) / 128, 4);
        k_node_pre<<<gp, 256, GRU_SMEM>>>(l);
        k_edge_tc<<<EDGE_BLOCKS, 256, EDGE_SMEM>>>(edge_index, b1, b2, l);
        dim3 gg((N_NODES + 127) / 128, 3, 2);
        k_gru_tc<<<gg, 256, GRU_SMEM>>>(b_ih, b_hh, l);
        k_gru_combine<<<(NEL + 255) / 256, 256>>>();
    }

    k_readout<<<625, 256, READ_SMEM>>>(Wr1, br1, Wr2, br2, out, out_size);
}